// round 13
// baseline (speedup 1.0000x reference)
#include <cuda_runtime.h>
#include <cuda_fp16.h>
#include <math.h>
#include <stdint.h>

#define NPOS    80
#define HID     128

// ---- device scratch ----
__device__ __half g_W1h[NPOS * 256 * HID];    // 5.25 MB fp16 copy of W1
__device__ float  g_Wp[3 * 4096 * 4];         // pre-paired W2/W3/W4 (192 KB)
__device__ int    g_msg_is64;

__device__ __forceinline__ float elu1(float x) {
    return x > 0.0f ? x : expm1f(x);
}

// ---- f32x2 packed helpers ----
__device__ __forceinline__ unsigned long long pk2(float lo, float hi) {
    unsigned long long r;
    asm("mov.b64 %0, {%1, %2};" : "=l"(r) : "f"(lo), "f"(hi));
    return r;
}
__device__ __forceinline__ void upk2(unsigned long long v, float& lo, float& hi) {
    asm("mov.b64 {%0, %1}, %2;" : "=f"(lo), "=f"(hi) : "l"(v));
}
__device__ __forceinline__ void fma2(unsigned long long& d,
                                     unsigned long long a, unsigned long long b) {
    asm("fma.rn.f32x2 %0, %1, %2, %0;" : "+l"(d) : "l"(a), "l"(b));
}
__device__ __forceinline__ void add2(unsigned long long& d, unsigned long long a) {
    asm("add.rn.f32x2 %0, %0, %1;" : "+l"(d) : "l"(a));
}
__device__ __forceinline__ unsigned long long h2f2(unsigned u) {
    float2 f = __half22float2(*(const __half2*)&u);
    return *(unsigned long long*)&f;
}

// ============================================================================
// Phase 0: W1 -> fp16, pre-pair W2/3/4, int64 detect. (Mostly DVFS-ramp time.)
// ============================================================================
#define CTHREADS 256
#define CW1BLOCKS 320
#define CPAIRBLOCKS 24
#define CBLOCKS (CW1BLOCKS + CPAIRBLOCKS)

__global__ __launch_bounds__(CTHREADS, 1)
void convert_kernel(const float* __restrict__ W1,
                    const float* __restrict__ W2,
                    const float* __restrict__ W3,
                    const float* __restrict__ W4,
                    const int* __restrict__ msg)
{
    const int bx = blockIdx.x;
    const int t  = threadIdx.x;

    if (bx == 0 && t < 32) {
        int v = 0;
        #pragma unroll 4
        for (int i = t; i < 2048; i += 32) v |= __ldg(&msg[2 * i + 1]);
        unsigned ball = __ballot_sync(0xFFFFFFFFu, v != 0);
        if (t == 0) g_msg_is64 = (ball == 0u) ? 1 : 0;
    }

    if (bx < CW1BLOCKS) {
        const int base = bx * CTHREADS + t;
        const int step = CW1BLOCKS * CTHREADS;
        float4 vv[8];
        #pragma unroll
        for (int j = 0; j < 8; j++) vv[j] = __ldg(&((const float4*)W1)[base + j * step]);
        #pragma unroll
        for (int j = 0; j < 8; j++) {
            __half2 h0 = __floats2half2_rn(vv[j].x, vv[j].y);
            __half2 h1 = __floats2half2_rn(vv[j].z, vv[j].w);
            uint2 o;
            o.x = *(unsigned*)&h0;
            o.y = *(unsigned*)&h1;
            ((uint2*)g_W1h)[base + j * step] = o;
        }
    } else {
        int task  = (bx - CW1BLOCKS) * CTHREADS + t;
        int layer = task >> 11;
        int i     = task & 2047;
        int k2 = i >> 5;
        int j  = i & 31;
        const float* Wsrc = (layer == 0) ? W2 : (layer == 1) ? W3 : W4;
        float4 a = __ldg(&((const float4*)Wsrc)[(2 * k2) * 32 + j]);
        float4 b = __ldg(&((const float4*)Wsrc)[(2 * k2 + 1) * 32 + j]);
        float4 pA; pA.x = a.x; pA.y = b.x; pA.z = a.y; pA.w = b.y;
        float4 pB; pB.x = a.z; pB.y = b.z; pB.z = a.w; pB.w = b.w;
        ((float4*)g_Wp)[layer * 4096 + i]        = pA;
        ((float4*)g_Wp)[layer * 4096 + 2048 + i] = pB;
    }
}

// ============================================================================
// Fused gather + MLP. TILE=28 rows, 448 threads, grid 293 ~= 2x148, occ 2.
// Gather: warp = 2 rows (lanes 0-15 row A, 16-31 row B), lane owns 16B of the
// 256B fp16 table row. Layer-0 weights prefetched BEFORE the gather loop.
// MLP: thread tile 2 rows x 4 cols, f32x2 over k-parity, pre-paired planes.
// ============================================================================
#define TILE 28
#define THREADS 448
// smem: planes 16384 floats (64KB) + hA 3584 (14KB) + hB 3584 (14KB)
#define SMEM_FLOATS (16384 + TILE * HID * 2)
#define SMEM_BYTES  (SMEM_FLOATS * 4)

__global__ __launch_bounds__(THREADS, 2)
void fused_kernel(const int* __restrict__ msg,
                  const float* __restrict__ b1,
                  const float* __restrict__ b2,
                  const float* __restrict__ b3,
                  const float* __restrict__ b4,
                  float* __restrict__ out, int B)
{
    extern __shared__ float smem[];
    float4*     plane4 = (float4*)smem;
    ulonglong2* planeU = (ulonglong2*)smem;
    float4*     hA4    = (float4*)(smem + 16384);
    float4*     hB4    = (float4*)(smem + 16384 + TILE * HID);
    unsigned char* msg_sh = (unsigned char*)hB4;    // 2240B; hB dead until L0 out

    const int t    = threadIdx.x;
    const int row0 = blockIdx.x * TILE;
    const int is64 = g_msg_is64;

    // ---- stage message bytes [r][p] into hB region ----
    for (int idx = t; idx < TILE * NPOS; idx += THREADS) {
        int r = idx / NPOS;
        int p = idx - r * NPOS;
        int row = row0 + r;
        int c = 0;
        if (row < B) {
            int gi = row * NPOS + p;
            c = is64 ? __ldg(&msg[2 * gi]) : __ldg(&msg[gi]);
        }
        msg_sh[idx] = (unsigned char)c;
    }
    __syncthreads();

    // ---- prefetch layer-0 weight planes (independent of gather) ----
    {
        const float4* Wg4 = (const float4*)g_Wp;      // layer 0
        #pragma unroll 2
        for (int i = t; i < 4096; i += THREADS) plane4[i] = __ldg(&Wg4[i]);
    }

    // ---- gather ----
    const int lane = t & 31;
    const int w    = t >> 5;              // 0..13
    const int hsel = lane >> 4;
    const int colg = lane & 15;
    const int rowL = w * 2 + hsel;        // 0..27

    {
        unsigned long long acc[4];
        {
            float4 b0 = __ldg(&((const float4*)b1)[colg * 2]);
            float4 b1v = __ldg(&((const float4*)b1)[colg * 2 + 1]);
            acc[0] = pk2(b0.x, b0.y);
            acc[1] = pk2(b0.z, b0.w);
            acc[2] = pk2(b1v.x, b1v.y);
            acc[3] = pk2(b1v.z, b1v.w);
        }

        const uint4* Wb = (const uint4*)g_W1h + colg;
        const unsigned* mrow = (const unsigned*)(msg_sh + rowL * NPOS);

        #pragma unroll 4
        for (int p4 = 0; p4 < NPOS / 4; p4++) {
            unsigned c4 = mrow[p4];
            #pragma unroll
            for (int i = 0; i < 4; i++) {
                int c = (c4 >> (8 * i)) & 255;
                int p = p4 * 4 + i;
                uint4 u = __ldg(Wb + (((p << 8) + c) << 4));
                add2(acc[0], h2f2(u.x));
                add2(acc[1], h2f2(u.y));
                add2(acc[2], h2f2(u.z));
                add2(acc[3], h2f2(u.w));
            }
        }

        float4 v0, v1; float lo, hi;
        upk2(acc[0], lo, hi); v0.x = elu1(lo); v0.y = elu1(hi);
        upk2(acc[1], lo, hi); v0.z = elu1(lo); v0.w = elu1(hi);
        upk2(acc[2], lo, hi); v1.x = elu1(lo); v1.y = elu1(hi);
        upk2(acc[3], lo, hi); v1.z = elu1(lo); v1.w = elu1(hi);
        hA4[rowL * 32 + colg * 2]     = v0;
        hA4[rowL * 32 + colg * 2 + 1] = v1;
    }
    __syncthreads();   // hA written, L0 planes staged, msg_sh reads done

    // ---- 3 dense layers ----
    const int j4 = t & 31;
    const int r0 = (t >> 5) * 2;          // 14 warps x 2 rows = 28

    const float* bg[3] = {b2, b3, b4};

    #pragma unroll 1
    for (int layer = 0; layer < 3; layer++) {
        const float4* hin  = (layer == 1) ? hB4 : hA4;
        float4*       hout = (layer == 1) ? hA4 : hB4;
        const bool    last = (layer == 2);

        if (layer > 0) {
            const float4* Wg4 = (const float4*)g_Wp + layer * 4096;
            #pragma unroll 2
            for (int i = t; i < 4096; i += THREADS) plane4[i] = __ldg(&Wg4[i]);
            __syncthreads();
        }

        unsigned long long a[2][4];
        {
            float4 bias = __ldg(&((const float4*)bg[layer])[j4]);
            #pragma unroll
            for (int r = 0; r < 2; r++) {
                a[r][0] = pk2(bias.x, 0.0f);
                a[r][1] = pk2(bias.y, 0.0f);
                a[r][2] = pk2(bias.z, 0.0f);
                a[r][3] = pk2(bias.w, 0.0f);
            }
        }

        #pragma unroll 4
        for (int k4 = 0; k4 < 32; k4++) {
            int k2 = 2 * k4;
            ulonglong2 wA0 = planeU[k2 * 32 + j4];
            ulonglong2 wB0 = planeU[2048 + k2 * 32 + j4];
            ulonglong2 wA1 = planeU[(k2 + 1) * 32 + j4];
            ulonglong2 wB1 = planeU[2048 + (k2 + 1) * 32 + j4];
            #pragma unroll
            for (int r = 0; r < 2; r++) {
                ulonglong2 hv = *(const ulonglong2*)&hin[(r0 + r) * 32 + k4];
                fma2(a[r][0], hv.x, wA0.x);
                fma2(a[r][1], hv.x, wA0.y);
                fma2(a[r][2], hv.x, wB0.x);
                fma2(a[r][3], hv.x, wB0.y);
                fma2(a[r][0], hv.y, wA1.x);
                fma2(a[r][1], hv.y, wA1.y);
                fma2(a[r][2], hv.y, wB1.x);
                fma2(a[r][3], hv.y, wB1.y);
            }
        }

        if (!last) {
            #pragma unroll
            for (int r = 0; r < 2; r++) {
                float4 v; float lo, hi;
                upk2(a[r][0], lo, hi); v.x = elu1(lo + hi);
                upk2(a[r][1], lo, hi); v.y = elu1(lo + hi);
                upk2(a[r][2], lo, hi); v.z = elu1(lo + hi);
                upk2(a[r][3], lo, hi); v.w = elu1(lo + hi);
                hout[(r0 + r) * 32 + j4] = v;
            }
            __syncthreads();   // hout done + plane reads done before restage
        } else {
            #pragma unroll
            for (int r = 0; r < 2; r++) {
                int row = row0 + r0 + r;
                if (row < B) {
                    float4 v; float lo, hi;
                    upk2(a[r][0], lo, hi); v.x = elu1(lo + hi);
                    upk2(a[r][1], lo, hi); v.y = elu1(lo + hi);
                    upk2(a[r][2], lo, hi); v.z = elu1(lo + hi);
                    upk2(a[r][3], lo, hi); v.w = elu1(lo + hi);
                    ((float4*)out)[row * 32 + j4] = v;
                }
            }
        }
    }
}

extern "C" void kernel_launch(void* const* d_in, const int* in_sizes, int n_in,
                              void* d_out, int out_size)
{
    const int*   msg = (const int*)  d_in[0];
    const float* W1  = (const float*)d_in[1];
    const float* b1  = (const float*)d_in[2];
    const float* W2  = (const float*)d_in[3];
    const float* b2  = (const float*)d_in[4];
    const float* W3  = (const float*)d_in[5];
    const float* b3  = (const float*)d_in[6];
    const float* W4  = (const float*)d_in[7];
    const float* b4  = (const float*)d_in[8];
    float* out = (float*)d_out;

    const int B = in_sizes[0] / NPOS;   // 8192

    cudaFuncSetAttribute(fused_kernel,
                         cudaFuncAttributeMaxDynamicSharedMemorySize, SMEM_BYTES);

    convert_kernel<<<CBLOCKS, CTHREADS>>>(W1, W2, W3, W4, msg);

    int grid = (B + TILE - 1) / TILE;   // 293
    fused_kernel<<<grid, THREADS, SMEM_BYTES>>>(msg, b1, b2, b3, b4, out, B);
}

// round 17
// speedup vs baseline: 1.1191x; 1.1191x over previous
#include <cuda_runtime.h>
#include <cuda_fp16.h>
#include <math.h>
#include <stdint.h>

#define NPOS    80
#define HID     128
#define MAXB    8192

// ---- device scratch ----
__device__ __half g_W1h[NPOS * 256 * HID];    // 5.25 MB fp16 copy of W1
__device__ float  g_Wp[3 * 4096 * 4];         // paired W2/W3/W4, [layer][k2][j2] float4
__device__ float  g_h0[(MAXB + 64) * HID];    // post-ELU h0
__device__ int    g_msg_is64;

__device__ __forceinline__ float elu1(float x) {
    return x > 0.0f ? x : expm1f(x);
}

// ---- f32x2 packed helpers ----
__device__ __forceinline__ unsigned long long pk2(float lo, float hi) {
    unsigned long long r;
    asm("mov.b64 %0, {%1, %2};" : "=l"(r) : "f"(lo), "f"(hi));
    return r;
}
__device__ __forceinline__ void upk2(unsigned long long v, float& lo, float& hi) {
    asm("mov.b64 {%0, %1}, %2;" : "=f"(lo), "=f"(hi) : "l"(v));
}
__device__ __forceinline__ void fma2(unsigned long long& d,
                                     unsigned long long a, unsigned long long b) {
    asm("fma.rn.f32x2 %0, %1, %2, %0;" : "+l"(d) : "l"(a), "l"(b));
}
__device__ __forceinline__ void add2(unsigned long long& d, unsigned long long a) {
    asm("add.rn.f32x2 %0, %0, %1;" : "+l"(d) : "l"(a));
}
__device__ __forceinline__ unsigned long long h2f2(unsigned u) {
    float2 f = __half22float2(*(const __half2*)&u);
    return *(unsigned long long*)&f;
}

// ============================================================================
// Phase 0: W1 -> fp16; pair W2/3/4 into [k2][j2] float4
//   entry(layer,k2,j2) = {W[2k2][2j2], W[2k2+1][2j2], W[2k2][2j2+1], W[2k2+1][2j2+1]}
// (each 8B half is a (k, k+1) pair for one column); int64 detect.
// ============================================================================
#define CTHREADS 256
#define CW1BLOCKS 320                 // 320*256*8 float4 = full W1
#define CPAIRBLOCKS 48                // 48*256 = 12288 pairing tasks
#define CBLOCKS (CW1BLOCKS + CPAIRBLOCKS)

__global__ __launch_bounds__(CTHREADS, 1)
void convert_kernel(const float* __restrict__ W1,
                    const float* __restrict__ W2,
                    const float* __restrict__ W3,
                    const float* __restrict__ W4,
                    const int* __restrict__ msg)
{
    const int bx = blockIdx.x;
    const int t  = threadIdx.x;

    if (bx == 0 && t < 32) {
        int v = 0;
        #pragma unroll 4
        for (int i = t; i < 2048; i += 32) v |= __ldg(&msg[2 * i + 1]);
        unsigned ball = __ballot_sync(0xFFFFFFFFu, v != 0);
        if (t == 0) g_msg_is64 = (ball == 0u) ? 1 : 0;
    }

    if (bx < CW1BLOCKS) {
        const int base = bx * CTHREADS + t;
        const int step = CW1BLOCKS * CTHREADS;
        float4 vv[8];
        #pragma unroll
        for (int j = 0; j < 8; j++) vv[j] = __ldg(&((const float4*)W1)[base + j * step]);
        #pragma unroll
        for (int j = 0; j < 8; j++) {
            __half2 h0 = __floats2half2_rn(vv[j].x, vv[j].y);
            __half2 h1 = __floats2half2_rn(vv[j].z, vv[j].w);
            uint2 o;
            o.x = *(unsigned*)&h0;
            o.y = *(unsigned*)&h1;
            ((uint2*)g_W1h)[base + j * step] = o;
        }
    } else {
        int task  = (bx - CW1BLOCKS) * CTHREADS + t;   // 0..12287
        int layer = task >> 12;                        // /4096
        int i     = task & 4095;
        int k2 = i >> 6;
        int j2 = i & 63;
        const float* Wsrc = (layer == 0) ? W2 : (layer == 1) ? W3 : W4;
        const float2* src = (const float2*)Wsrc;
        float2 a = __ldg(&src[(2 * k2) * 64 + j2]);
        float2 b = __ldg(&src[(2 * k2 + 1) * 64 + j2]);
        float4 e; e.x = a.x; e.y = b.x; e.z = a.y; e.w = b.y;
        ((float4*)g_Wp)[layer * 4096 + i] = e;
    }
}

// ============================================================================
// Phase 1: gather (fp16 table, f32x2 accumulate). 512 CTAs x 8 warps,
// warp = 2 rows, lane owns 16B (8 hid cols) of the 256B fp16 row.
// ============================================================================
#define GTILE 16
#define GTHREADS 256

__global__ __launch_bounds__(GTHREADS)
void gather_kernel(const int* __restrict__ msg,
                   const float* __restrict__ b1, int B)
{
    __shared__ unsigned char msg_sh[GTILE * NPOS];   // [r][p]

    const int t    = threadIdx.x;
    const int row0 = blockIdx.x * GTILE;
    const int is64 = g_msg_is64;

    for (int idx = t; idx < GTILE * NPOS; idx += GTHREADS) {
        int r = idx / NPOS;
        int p = idx - r * NPOS;
        int row = row0 + r;
        int c = 0;
        if (row < B) {
            int gi = row * NPOS + p;
            c = is64 ? __ldg(&msg[2 * gi]) : __ldg(&msg[gi]);
        }
        msg_sh[idx] = (unsigned char)c;
    }
    __syncthreads();

    const int lane = t & 31;
    const int w    = t >> 5;
    const int hsel = lane >> 4;
    const int colg = lane & 15;
    const int rowL = w * 2 + hsel;

    unsigned long long acc[4];
    {
        float4 b0 = __ldg(&((const float4*)b1)[colg * 2]);
        float4 b1v = __ldg(&((const float4*)b1)[colg * 2 + 1]);
        acc[0] = pk2(b0.x, b0.y);
        acc[1] = pk2(b0.z, b0.w);
        acc[2] = pk2(b1v.x, b1v.y);
        acc[3] = pk2(b1v.z, b1v.w);
    }

    const uint4* Wb = (const uint4*)g_W1h + colg;
    const unsigned* mrow = (const unsigned*)(msg_sh + rowL * NPOS);

    #pragma unroll 4
    for (int p4 = 0; p4 < NPOS / 4; p4++) {
        unsigned c4 = mrow[p4];
        #pragma unroll
        for (int i = 0; i < 4; i++) {
            int c = (c4 >> (8 * i)) & 255;
            int p = p4 * 4 + i;
            uint4 u = __ldg(Wb + (((p << 8) + c) << 4));
            add2(acc[0], h2f2(u.x));
            add2(acc[1], h2f2(u.y));
            add2(acc[2], h2f2(u.z));
            add2(acc[3], h2f2(u.w));
        }
    }

    int row = row0 + rowL;
    if (row < B) {
        float4 v0, v1; float lo, hi;
        upk2(acc[0], lo, hi); v0.x = elu1(lo); v0.y = elu1(hi);
        upk2(acc[1], lo, hi); v0.z = elu1(lo); v0.w = elu1(hi);
        upk2(acc[2], lo, hi); v1.x = elu1(lo); v1.y = elu1(hi);
        upk2(acc[3], lo, hi); v1.z = elu1(lo); v1.w = elu1(hi);
        ((float4*)g_h0)[row * 32 + colg * 2]     = v0;
        ((float4*)g_h0)[row * 32 + colg * 2 + 1] = v1;
    }
}

// ============================================================================
// Phase 2: 3 dense layers. MTILE 56, 448 threads, occ 1, grid 147.
// Thread tile: 8 rows x 2 cols (warp = 8 rows x 64 cols) -> weight-plane LDS
// traffic ~2x lower than 4x4 (no longer co-binding with FMA).
// Double-buffered planes: next layer's weights prefetched to regs before the
// FMA loop, STS'd after it.
// ============================================================================
#define MTILE 56
#define MTHREADS 448
// floats: plane0 16384 + plane1 16384 + hA 7168 + hB 7168 = 47104 (184 KB)
#define MSMEM_FLOATS (16384 * 2 + MTILE * HID * 2)
#define MSMEM_BYTES  (MSMEM_FLOATS * 4)

__global__ __launch_bounds__(MTHREADS, 1)
void mlp_kernel(const float* __restrict__ b2,
                const float* __restrict__ b3,
                const float* __restrict__ b4,
                float* __restrict__ out, int B)
{
    extern __shared__ float smem[];
    float4* plane0 = (float4*)smem;
    float4* plane1 = (float4*)(smem + 16384);
    float4* hA4    = (float4*)(smem + 32768);
    float4* hB4    = (float4*)(smem + 32768 + MTILE * HID);

    const int t    = threadIdx.x;
    const int row0 = blockIdx.x * MTILE;

    // load h0 tile + stage layer-0 planes
    for (int idx = t; idx < MTILE * 32; idx += MTHREADS) {
        hA4[idx] = ((const float4*)g_h0)[row0 * 32 + idx];
    }
    {
        const float4* Wg4 = (const float4*)g_Wp;
        #pragma unroll
        for (int j = 0; j < 10; j++) {
            int i = t + j * MTHREADS;
            if (i < 4096) plane0[i] = __ldg(&Wg4[i]);
        }
    }
    __syncthreads();

    const int w    = t >> 5;
    const int lane = t & 31;
    const int rowg = w % 7;              // row group (8 rows)
    const int colh = w / 7;              // column half
    const int r0   = rowg * 8;
    const int j2   = colh * 32 + lane;   // column-pair index: cols 2j2, 2j2+1

    const float* bg[3] = {b2, b3, b4};

    #pragma unroll 1
    for (int layer = 0; layer < 3; layer++) {
        const float4* pcur  = (layer & 1) ? plane1 : plane0;
        float4*       pnext = (layer & 1) ? plane0 : plane1;
        const float4* hin   = (layer == 1) ? hB4 : hA4;
        float4*       hout  = (layer == 1) ? hA4 : hB4;
        const bool    last  = (layer == 2);

        // prefetch next layer's planes into registers (latency hides under FMA)
        float4 pre[10];
        if (!last) {
            const float4* Wn = (const float4*)g_Wp + (layer + 1) * 4096;
            #pragma unroll
            for (int j = 0; j < 10; j++) {
                int i = t + j * MTHREADS;
                if (i < 4096) pre[j] = __ldg(&Wn[i]);
            }
        }

        unsigned long long acc[8][2];
        {
            float2 bb = __ldg(&((const float2*)bg[layer])[j2]);
            #pragma unroll
            for (int r = 0; r < 8; r++) {
                acc[r][0] = pk2(bb.x, 0.0f);
                acc[r][1] = pk2(bb.y, 0.0f);
            }
        }

        #pragma unroll 4
        for (int k4 = 0; k4 < 32; k4++) {
            int k2 = 2 * k4;
            ulonglong2 W0 = *(const ulonglong2*)&pcur[k2 * 64 + j2];
            ulonglong2 W1 = *(const ulonglong2*)&pcur[(k2 + 1) * 64 + j2];
            #pragma unroll
            for (int r = 0; r < 8; r++) {
                ulonglong2 hv = *(const ulonglong2*)&hin[(r0 + r) * 32 + k4];
                fma2(acc[r][0], hv.x, W0.x);
                fma2(acc[r][1], hv.x, W0.y);
                fma2(acc[r][0], hv.y, W1.x);
                fma2(acc[r][1], hv.y, W1.y);
            }
        }

        // commit prefetched planes (their last readers finished before the
        // barrier at the top of this layer)
        if (!last) {
            #pragma unroll
            for (int j = 0; j < 10; j++) {
                int i = t + j * MTHREADS;
                if (i < 4096) pnext[i] = pre[j];
            }
        }

        if (!last) {
            #pragma unroll
            for (int r = 0; r < 8; r++) {
                float lo, hi; float2 v;
                upk2(acc[r][0], lo, hi); v.x = elu1(lo + hi);
                upk2(acc[r][1], lo, hi); v.y = elu1(lo + hi);
                ((float2*)hout)[(r0 + r) * 64 + j2] = v;
            }
            __syncthreads();   // hout + pnext visible; pcur reads done
        } else {
            #pragma unroll
            for (int r = 0; r < 8; r++) {
                int row = row0 + r0 + r;
                if (row < B) {
                    float lo, hi; float2 v;
                    upk2(acc[r][0], lo, hi); v.x = elu1(lo + hi);
                    upk2(acc[r][1], lo, hi); v.y = elu1(lo + hi);
                    ((float2*)out)[row * 64 + j2] = v;
                }
            }
        }
    }
}

extern "C" void kernel_launch(void* const* d_in, const int* in_sizes, int n_in,
                              void* d_out, int out_size)
{
    const int*   msg = (const int*)  d_in[0];
    const float* W1  = (const float*)d_in[1];
    const float* b1  = (const float*)d_in[2];
    const float* W2  = (const float*)d_in[3];
    const float* b2  = (const float*)d_in[4];
    const float* W3  = (const float*)d_in[5];
    const float* b3  = (const float*)d_in[6];
    const float* W4  = (const float*)d_in[7];
    const float* b4  = (const float*)d_in[8];
    float* out = (float*)d_out;

    const int B = in_sizes[0] / NPOS;   // 8192

    cudaFuncSetAttribute(mlp_kernel,
                         cudaFuncAttributeMaxDynamicSharedMemorySize, MSMEM_BYTES);

    convert_kernel<<<CBLOCKS, CTHREADS>>>(W1, W2, W3, W4, msg);

    int ggrid = (B + GTILE - 1) / GTILE;   // 512
    gather_kernel<<<ggrid, GTHREADS>>>(msg, b1, B);

    int mgrid = (B + MTILE - 1) / MTILE;   // 147
    mlp_kernel<<<mgrid, MTHREADS, MSMEM_BYTES>>>(b2, b3, b4, out, B);
}